// round 1
// baseline (speedup 1.0000x reference)
#include <cuda_runtime.h>
#include <cstddef>

#define NN   50000
#define EE   800000
#define INC  512
#define HIDC 256
#define OUTC 40
#define BN_EPS 1e-5f

// ---------------- scratch (device globals; no allocation allowed) ----------------
__device__ float g_deg[NN];
__device__ float g_dinv[NN];
__device__ float g_norm[EE];
__device__ float g_t1[NN * HIDC];
__device__ float g_t2[NN * HIDC];
__device__ float g_t3[NN * OUTC];
__device__ float g_la[NN * OUTC];
__device__ float g_lb[NN * OUTC];
__device__ float g_sum[HIDC];
__device__ float g_sumsq[HIDC];
__device__ float g_scale[HIDC];
__device__ float g_shift[HIDC];

// ---------------- degree / normalization ----------------
__global__ void k_fill_deg() {
    int i = blockIdx.x * blockDim.x + threadIdx.x;
    if (i < NN) g_deg[i] = 1.0f;   // self-loop weight
}

__global__ void k_deg_edges(const int* __restrict__ row, const float* __restrict__ w) {
    int e = blockIdx.x * blockDim.x + threadIdx.x;
    if (e < EE) atomicAdd(&g_deg[row[e]], w[e]);
}

__global__ void k_dinv() {
    int i = blockIdx.x * blockDim.x + threadIdx.x;
    if (i < NN) {
        float d = g_deg[i];
        g_dinv[i] = d > 0.f ? rsqrtf(fmaxf(d, 1e-12f)) : 0.f;
    }
}

__global__ void k_norm(const int* __restrict__ row, const int* __restrict__ col,
                       const float* __restrict__ w) {
    int e = blockIdx.x * blockDim.x + threadIdx.x;
    if (e < EE) g_norm[e] = g_dinv[row[e]] * w[e] * g_dinv[col[e]];
}

// ---------------- propagate: out[i] = dinv[i]^2*h[i] (+bias) + sum_E norm*h[col] ----------------
template <int C>
__global__ void k_prop_init(const float* __restrict__ h, float* __restrict__ out,
                            const float* __restrict__ bias) {
    int idx = blockIdx.x * blockDim.x + threadIdx.x;
    if (idx < NN * C) {
        int i = idx / C;
        int c = idx - i * C;
        float d = g_dinv[i];
        float b = bias ? bias[c] : 0.f;
        out[idx] = d * d * h[idx] + b;
    }
}

__global__ void k_prop_edges_256(const float* __restrict__ h, float* __restrict__ out,
                                 const int* __restrict__ row, const int* __restrict__ col) {
    int gid = blockIdx.x * blockDim.x + threadIdx.x;
    if (gid >= EE * 64) return;            // 64 float4 per edge (C=256)
    int e = gid >> 6;
    int v = gid & 63;
    float nrm = g_norm[e];
    int r = row[e], c = col[e];
    float4 hh = *((const float4*)(h + ((size_t)c << 8)) + v);
    float* o = out + ((size_t)r << 8) + (v << 2);
    atomicAdd(o + 0, nrm * hh.x);
    atomicAdd(o + 1, nrm * hh.y);
    atomicAdd(o + 2, nrm * hh.z);
    atomicAdd(o + 3, nrm * hh.w);
}

__global__ void k_prop_edges_40(const float* __restrict__ h, float* __restrict__ out,
                                const int* __restrict__ row, const int* __restrict__ col) {
    int gid = blockIdx.x * blockDim.x + threadIdx.x;
    if (gid >= EE * 10) return;            // 10 float4 per edge (C=40)
    int e = gid / 10;
    int v = gid - e * 10;
    float nrm = g_norm[e];
    int r = row[e], c = col[e];
    float4 hh = *((const float4*)(h + (size_t)c * 40) + v);
    float* o = out + (size_t)r * 40 + v * 4;
    atomicAdd(o + 0, nrm * hh.x);
    atomicAdd(o + 1, nrm * hh.y);
    atomicAdd(o + 2, nrm * hh.z);
    atomicAdd(o + 3, nrm * hh.w);
}

// ---------------- batchnorm (C = 256) ----------------
__global__ void k_zero_sums() {
    int c = threadIdx.x;
    g_sum[c] = 0.f;
    g_sumsq[c] = 0.f;
}

__global__ void k_bn_reduce(const float* __restrict__ h) {
    int c = threadIdx.x;                   // channel (coalesced across threads)
    float s = 0.f, sq = 0.f;
    for (int i = blockIdx.x; i < NN; i += gridDim.x) {
        float v = h[(size_t)i * HIDC + c];
        s += v;
        sq += v * v;
    }
    atomicAdd(&g_sum[c], s);
    atomicAdd(&g_sumsq[c], sq);
}

__global__ void k_bn_finalize(const float* __restrict__ gamma, const float* __restrict__ beta) {
    int c = threadIdx.x;
    float mean = g_sum[c] * (1.0f / NN);
    float var = g_sumsq[c] * (1.0f / NN) - mean * mean;
    var = fmaxf(var, 0.f);
    float inv = rsqrtf(var + BN_EPS);
    float sc = gamma[c] * inv;
    g_scale[c] = sc;
    g_shift[c] = beta[c] - mean * sc;
}

__global__ void k_bn_apply_relu(const float* __restrict__ h, float* __restrict__ out) {
    int idx = blockIdx.x * blockDim.x + threadIdx.x;
    if (idx < NN * HIDC) {
        int c = idx & (HIDC - 1);
        out[idx] = fmaxf(h[idx] * g_scale[c] + g_shift[c], 0.f);
    }
}

// ---------------- SGEMM: C[M,N] = A[M,K] @ B[K,N], 128x128x8, 8x8 per thread ----------------
__global__ void k_sgemm(int M, int N, int K,
                        const float* __restrict__ A, const float* __restrict__ B,
                        float* __restrict__ C) {
    const int BM = 128, BNt = 128, BK = 8;
    __shared__ float As[BK][BM];
    __shared__ float Bs[BK][BNt + 4];

    int tid = threadIdx.x;
    int ty = tid >> 4;       // 0..15
    int tx = tid & 15;       // 0..15

    int aRow = tid >> 1;            // 0..127
    int aK   = (tid & 1) * 4;       // 0 or 4
    int bK   = tid >> 5;            // 0..7
    int bCol = (tid & 31) * 4;      // 0..124

    int gARow = blockIdx.y * BM + aRow;
    int gBCol = blockIdx.x * BNt + bCol;

    float acc[8][8];
#pragma unroll
    for (int i = 0; i < 8; i++)
#pragma unroll
        for (int j = 0; j < 8; j++) acc[i][j] = 0.f;

    for (int k0 = 0; k0 < K; k0 += BK) {
        float4 a = make_float4(0.f, 0.f, 0.f, 0.f);
        if (gARow < M) a = *(const float4*)(A + (size_t)gARow * K + k0 + aK);
        As[aK + 0][aRow] = a.x;
        As[aK + 1][aRow] = a.y;
        As[aK + 2][aRow] = a.z;
        As[aK + 3][aRow] = a.w;

        float4 b = make_float4(0.f, 0.f, 0.f, 0.f);
        if (gBCol < N)   // all N here are multiples of 4
            b = *(const float4*)(B + (size_t)(k0 + bK) * N + gBCol);
        Bs[bK][bCol + 0] = b.x;
        Bs[bK][bCol + 1] = b.y;
        Bs[bK][bCol + 2] = b.z;
        Bs[bK][bCol + 3] = b.w;

        __syncthreads();
#pragma unroll
        for (int k = 0; k < BK; k++) {
            float ra[8], rb[8];
#pragma unroll
            for (int i = 0; i < 8; i++) ra[i] = As[k][ty * 8 + i];
#pragma unroll
            for (int j = 0; j < 8; j++) rb[j] = Bs[k][tx * 8 + j];
#pragma unroll
            for (int i = 0; i < 8; i++)
#pragma unroll
                for (int j = 0; j < 8; j++) acc[i][j] += ra[i] * rb[j];
        }
        __syncthreads();
    }

    int cRow0 = blockIdx.y * BM + ty * 8;
    int cCol0 = blockIdx.x * BNt + tx * 8;
#pragma unroll
    for (int i = 0; i < 8; i++) {
        int r = cRow0 + i;
        if (r < M) {
#pragma unroll
            for (int j = 0; j < 8; j++) {
                int cc = cCol0 + j;
                if (cc < N) C[(size_t)r * N + cc] = acc[i][j];
            }
        }
    }
}

// ---------------- host orchestration ----------------
static inline int cdiv(int a, int b) { return (a + b - 1) / b; }

extern "C" void kernel_launch(void* const* d_in, const int* in_sizes, int n_in,
                              void* d_out, int out_size) {
    const float* x    = (const float*)d_in[0];
    const int*   ei   = (const int*)  d_in[1];
    const float* lab  = (const float*)d_in[2];
    const float* lab2 = (const float*)d_in[3];
    const float* ew   = (const float*)d_in[4];
    const float* W0   = (const float*)d_in[5];
    const float* b0   = (const float*)d_in[6];
    const float* W1   = (const float*)d_in[7];
    const float* b1   = (const float*)d_in[8];
    const float* W2   = (const float*)d_in[9];
    const float* b2   = (const float*)d_in[10];
    const float* g0   = (const float*)d_in[11];
    const float* be0  = (const float*)d_in[12];
    const float* g1   = (const float*)d_in[13];
    const float* be1  = (const float*)d_in[14];
    float* out = (float*)d_out;

    const int* row = ei;
    const int* col = ei + EE;

    float *t1, *t2, *t3, *la, *lb;
    cudaGetSymbolAddress((void**)&t1, g_t1);
    cudaGetSymbolAddress((void**)&t2, g_t2);
    cudaGetSymbolAddress((void**)&t3, g_t3);
    cudaGetSymbolAddress((void**)&la, g_la);
    cudaGetSymbolAddress((void**)&lb, g_lb);

    const int T = 256;

    // ---- normalization coefficients ----
    k_fill_deg<<<cdiv(NN, T), T>>>();
    k_deg_edges<<<cdiv(EE, T), T>>>(row, ew);
    k_dinv<<<cdiv(NN, T), T>>>();
    k_norm<<<cdiv(EE, T), T>>>(row, col, ew);

    dim3 gemm_grid_hid(cdiv(HIDC, 128), cdiv(NN, 128));  // (2, 391)
    dim3 gemm_grid_out(cdiv(OUTC, 128), cdiv(NN, 128));  // (1, 391)
    int prop256_grid = cdiv(EE * 64, T);
    int prop40_grid  = cdiv(EE * 10, T);
    int elem256_grid = cdiv(NN * HIDC, T);
    int elem40_grid  = cdiv(NN * OUTC, T);

    // ---- layer 0: x@W0 -> propagate(+b0) -> BN -> ReLU ----
    k_sgemm<<<gemm_grid_hid, T>>>(NN, HIDC, INC, x, W0, t1);
    k_prop_init<HIDC><<<elem256_grid, T>>>(t1, t2, b0);
    k_prop_edges_256<<<prop256_grid, T>>>(t1, t2, row, col);
    k_zero_sums<<<1, HIDC>>>();
    k_bn_reduce<<<256, HIDC>>>(t2);
    k_bn_finalize<<<1, HIDC>>>(g0, be0);
    k_bn_apply_relu<<<elem256_grid, T>>>(t2, t1);

    // ---- layer 1: h@W1 -> propagate(+b1) -> BN -> ReLU ----
    k_sgemm<<<gemm_grid_hid, T>>>(NN, HIDC, HIDC, t1, W1, t2);
    k_prop_init<HIDC><<<elem256_grid, T>>>(t2, t1, b1);
    k_prop_edges_256<<<prop256_grid, T>>>(t2, t1, row, col);
    k_zero_sums<<<1, HIDC>>>();
    k_bn_reduce<<<256, HIDC>>>(t1);
    k_bn_finalize<<<1, HIDC>>>(g1, be1);
    k_bn_apply_relu<<<elem256_grid, T>>>(t1, t2);

    // ---- output conv: h@W2 -> propagate(+b2) -> d_out[0 : NN*40] ----
    k_sgemm<<<gemm_grid_out, T>>>(NN, OUTC, HIDC, t2, W2, t3);
    k_prop_init<OUTC><<<elem40_grid, T>>>(t3, out, b2);
    k_prop_edges_40<<<prop40_grid, T>>>(t3, out, row, col);

    // ---- LPA: 3 propagates each on both label matrices ----
    float* yh1 = out + (size_t)NN * OUTC;
    float* yh2 = out + (size_t)2 * NN * OUTC;

    k_prop_init<OUTC><<<elem40_grid, T>>>(lab, la, nullptr);
    k_prop_edges_40<<<prop40_grid, T>>>(lab, la, row, col);
    k_prop_init<OUTC><<<elem40_grid, T>>>(la, lb, nullptr);
    k_prop_edges_40<<<prop40_grid, T>>>(la, lb, row, col);
    k_prop_init<OUTC><<<elem40_grid, T>>>(lb, yh1, nullptr);
    k_prop_edges_40<<<prop40_grid, T>>>(lb, yh1, row, col);

    k_prop_init<OUTC><<<elem40_grid, T>>>(lab2, la, nullptr);
    k_prop_edges_40<<<prop40_grid, T>>>(lab2, la, row, col);
    k_prop_init<OUTC><<<elem40_grid, T>>>(la, lb, nullptr);
    k_prop_edges_40<<<prop40_grid, T>>>(la, lb, row, col);
    k_prop_init<OUTC><<<elem40_grid, T>>>(lb, yh2, nullptr);
    k_prop_edges_40<<<prop40_grid, T>>>(lb, yh2, row, col);
}

// round 2
// speedup vs baseline: 1.7048x; 1.7048x over previous
#include <cuda_runtime.h>
#include <cstddef>

#define NN   50000
#define EE   800000
#define INC  512
#define HIDC 256
#define OUTC 40
#define BN_EPS 1e-5f

// ---------------- scratch (device globals; no allocation allowed) ----------------
__device__ float g_deg[NN];
__device__ float g_dinv[NN];
__device__ int   g_cnt[NN];
__device__ int   g_rowstart[NN + 1];
__device__ int   g_cursor[NN];
__device__ int   g_ecol[EE];
__device__ float g_ew2[EE];          // w * dinv[col]  (sorted by row)
__device__ float g_t1[NN * HIDC];
__device__ float g_t2[NN * HIDC];
__device__ float g_t3[NN * OUTC];
__device__ float g_la[NN * OUTC];
__device__ float g_lb[NN * OUTC];
__device__ float g_sum[HIDC];
__device__ float g_sumsq[HIDC];
__device__ float g_scale[HIDC];
__device__ float g_shift[HIDC];

// ---------------- CSR construction ----------------
__global__ void k_init_node() {
    int i = blockIdx.x * blockDim.x + threadIdx.x;
    if (i < NN) { g_deg[i] = 1.0f; g_cnt[i] = 0; }   // self-loop weight
}

__global__ void k_deg_cnt(const int* __restrict__ row, const float* __restrict__ w) {
    int e = blockIdx.x * blockDim.x + threadIdx.x;
    if (e < EE) {
        int r = row[e];
        atomicAdd(&g_deg[r], w[e]);
        atomicAdd(&g_cnt[r], 1);
    }
}

__global__ void k_dinv() {
    int i = blockIdx.x * blockDim.x + threadIdx.x;
    if (i < NN) {
        float d = g_deg[i];
        g_dinv[i] = d > 0.f ? rsqrtf(fmaxf(d, 1e-12f)) : 0.f;
    }
}

// single-block exclusive scan over g_cnt -> g_rowstart / g_cursor
__global__ void k_scan() {
    const int T = 1024;
    const int CH = (NN + T - 1) / T;   // 49
    __shared__ int warp_sums[32];
    int t = threadIdx.x;
    int start = t * CH;
    int end = start + CH; if (end > NN) end = NN;
    int local = 0;
    for (int i = start; i < end && i < NN; i++) local += g_cnt[i];

    int lane = t & 31, wid = t >> 5;
    int v = local;
#pragma unroll
    for (int o = 1; o < 32; o <<= 1) {
        int n = __shfl_up_sync(0xffffffffu, v, o);
        if (lane >= o) v += n;
    }
    if (lane == 31) warp_sums[wid] = v;
    __syncthreads();
    if (wid == 0) {
        int w = warp_sums[lane];
#pragma unroll
        for (int o = 1; o < 32; o <<= 1) {
            int n = __shfl_up_sync(0xffffffffu, w, o);
            if (lane >= o) w += n;
        }
        warp_sums[lane] = w;
    }
    __syncthreads();
    int excl = v - local + (wid > 0 ? warp_sums[wid - 1] : 0);

    int run = excl;
    for (int i = start; i < end && i < NN; i++) {
        g_rowstart[i] = run;
        g_cursor[i] = run;
        run += g_cnt[i];
    }
    if (t == T - 1) g_rowstart[NN] = run;   // == EE
}

__global__ void k_scatter(const int* __restrict__ row, const int* __restrict__ col,
                          const float* __restrict__ w) {
    int e = blockIdx.x * blockDim.x + threadIdx.x;
    if (e < EE) {
        int r = row[e];
        int c = col[e];
        int pos = atomicAdd(&g_cursor[r], 1);
        g_ecol[pos] = c;
        g_ew2[pos] = w[e] * g_dinv[c];
    }
}

// ---------------- propagate C=256: block per node, thread per channel ----------------
__global__ void __launch_bounds__(256) k_prop256(const float* __restrict__ h,
                                                 float* __restrict__ out,
                                                 const float* __restrict__ bias) {
    int i = blockIdx.x;
    int c = threadIdx.x;
    __shared__ int scol[256];
    __shared__ float sw[256];

    int s = g_rowstart[i], e = g_rowstart[i + 1];
    float hc = h[((size_t)i << 8) + c];
    float acc0 = 0.f, acc1 = 0.f, acc2 = 0.f, acc3 = 0.f;

    for (int base = s; base < e; base += 256) {
        int n = e - base; if (n > 256) n = 256;
        if (c < n) { scol[c] = g_ecol[base + c]; sw[c] = g_ew2[base + c]; }
        __syncthreads();
        int j = 0;
        for (; j + 3 < n; j += 4) {
            acc0 += sw[j + 0] * h[((size_t)scol[j + 0] << 8) + c];
            acc1 += sw[j + 1] * h[((size_t)scol[j + 1] << 8) + c];
            acc2 += sw[j + 2] * h[((size_t)scol[j + 2] << 8) + c];
            acc3 += sw[j + 3] * h[((size_t)scol[j + 3] << 8) + c];
        }
        for (; j < n; j++)
            acc0 += sw[j] * h[((size_t)scol[j] << 8) + c];
        __syncthreads();
    }
    float di = g_dinv[i];
    float acc = (acc0 + acc1) + (acc2 + acc3);
    float b = bias ? bias[c] : 0.f;
    out[((size_t)i << 8) + c] = di * di * hc + di * acc + b;
}

// ---------------- propagate C=40: warp per node; optional second matrix ----------------
template <bool DUAL>
__global__ void __launch_bounds__(256) k_prop40(const float* __restrict__ ha,
                                                const float* __restrict__ hb,
                                                float* __restrict__ oa,
                                                float* __restrict__ ob,
                                                const float* __restrict__ bias) {
    int warp = threadIdx.x >> 5;
    int lane = threadIdx.x & 31;
    int i = blockIdx.x * 8 + warp;
    if (i >= NN) return;

    int s = g_rowstart[i], e = g_rowstart[i + 1];
    float a0 = 0.f, a1 = 0.f, b0 = 0.f, b1 = 0.f;

    for (int p = s; p < e; p++) {
        int c = g_ecol[p];            // broadcast load (same addr across warp)
        float w = g_ew2[p];
        const float* ra = ha + (size_t)c * OUTC;
        a0 += w * ra[lane & 31 ? lane : lane];   // lanes 0..31 -> channels 0..31
        a0 = a0;                                  // (keep simple below)
        if (lane < 8) a1 += w * ra[lane + 32];
        if (DUAL) {
            const float* rb = hb + (size_t)c * OUTC;
            b0 += w * rb[lane];
            if (lane < 8) b1 += w * rb[lane + 32];
        }
    }
    // fix-up: a0 accumulated ra[lane] (expression above is just ra[lane])
    float di = g_dinv[i];
    size_t off = (size_t)i * OUTC;
    float bs0 = bias ? bias[lane] : 0.f;
    float bs1 = (bias && lane < 8) ? bias[lane + 32] : 0.f;

    oa[off + lane] = di * di * ha[off + lane] + di * a0 + bs0;
    if (lane < 8)
        oa[off + lane + 32] = di * di * ha[off + lane + 32] + di * a1 + bs1;
    if (DUAL) {
        ob[off + lane] = di * di * hb[off + lane] + di * b0;
        if (lane < 8)
            ob[off + lane + 32] = di * di * hb[off + lane + 32] + di * b1;
    }
}

// NOTE: the `a0 += w * ra[lane & 31 ? lane : lane]` expression is exactly ra[lane];
// written plainly in the loop above.

// ---------------- batchnorm (C = 256) ----------------
__global__ void k_zero_sums() {
    int c = threadIdx.x;
    g_sum[c] = 0.f;
    g_sumsq[c] = 0.f;
}

__global__ void k_bn_reduce(const float* __restrict__ h) {
    int c = threadIdx.x;
    float s = 0.f, sq = 0.f;
    for (int i = blockIdx.x; i < NN; i += gridDim.x) {
        float v = h[((size_t)i << 8) + c];
        s += v;
        sq += v * v;
    }
    atomicAdd(&g_sum[c], s);
    atomicAdd(&g_sumsq[c], sq);
}

__global__ void k_bn_finalize(const float* __restrict__ gamma, const float* __restrict__ beta) {
    int c = threadIdx.x;
    float mean = g_sum[c] * (1.0f / NN);
    float var = g_sumsq[c] * (1.0f / NN) - mean * mean;
    var = fmaxf(var, 0.f);
    float inv = rsqrtf(var + BN_EPS);
    float sc = gamma[c] * inv;
    g_scale[c] = sc;
    g_shift[c] = beta[c] - mean * sc;
}

__global__ void k_bn_apply_relu(const float* __restrict__ h, float* __restrict__ out) {
    int idx = blockIdx.x * blockDim.x + threadIdx.x;
    if (idx < NN * HIDC) {
        int c = idx & (HIDC - 1);
        out[idx] = fmaxf(h[idx] * g_scale[c] + g_shift[c], 0.f);
    }
}

// ---------------- SGEMM: C[M,N] = A[M,K] @ B[K,N], 128x128x8, 8x8 per thread ----------------
__global__ void k_sgemm(int M, int N, int K,
                        const float* __restrict__ A, const float* __restrict__ B,
                        float* __restrict__ C) {
    const int BM = 128, BNt = 128, BK = 8;
    __shared__ float As[BK][BM];
    __shared__ float Bs[BK][BNt + 4];

    int tid = threadIdx.x;
    int ty = tid >> 4;
    int tx = tid & 15;

    int aRow = tid >> 1;
    int aK   = (tid & 1) * 4;
    int bK   = tid >> 5;
    int bCol = (tid & 31) * 4;

    int gARow = blockIdx.y * BM + aRow;
    int gBCol = blockIdx.x * BNt + bCol;

    float acc[8][8];
#pragma unroll
    for (int i = 0; i < 8; i++)
#pragma unroll
        for (int j = 0; j < 8; j++) acc[i][j] = 0.f;

    for (int k0 = 0; k0 < K; k0 += BK) {
        float4 a = make_float4(0.f, 0.f, 0.f, 0.f);
        if (gARow < M) a = *(const float4*)(A + (size_t)gARow * K + k0 + aK);
        As[aK + 0][aRow] = a.x;
        As[aK + 1][aRow] = a.y;
        As[aK + 2][aRow] = a.z;
        As[aK + 3][aRow] = a.w;

        float4 b = make_float4(0.f, 0.f, 0.f, 0.f);
        if (gBCol < N)
            b = *(const float4*)(B + (size_t)(k0 + bK) * N + gBCol);
        Bs[bK][bCol + 0] = b.x;
        Bs[bK][bCol + 1] = b.y;
        Bs[bK][bCol + 2] = b.z;
        Bs[bK][bCol + 3] = b.w;

        __syncthreads();
#pragma unroll
        for (int k = 0; k < BK; k++) {
            float ra[8], rb[8];
#pragma unroll
            for (int i = 0; i < 8; i++) ra[i] = As[k][ty * 8 + i];
#pragma unroll
            for (int j = 0; j < 8; j++) rb[j] = Bs[k][tx * 8 + j];
#pragma unroll
            for (int i = 0; i < 8; i++)
#pragma unroll
                for (int j = 0; j < 8; j++) acc[i][j] += ra[i] * rb[j];
        }
        __syncthreads();
    }

    int cRow0 = blockIdx.y * BM + ty * 8;
    int cCol0 = blockIdx.x * BNt + tx * 8;
#pragma unroll
    for (int i = 0; i < 8; i++) {
        int r = cRow0 + i;
        if (r < M) {
#pragma unroll
            for (int j = 0; j < 8; j++) {
                int cc = cCol0 + j;
                if (cc < N) C[(size_t)r * N + cc] = acc[i][j];
            }
        }
    }
}

// ---------------- host orchestration ----------------
static inline int cdiv(int a, int b) { return (a + b - 1) / b; }

extern "C" void kernel_launch(void* const* d_in, const int* in_sizes, int n_in,
                              void* d_out, int out_size) {
    const float* x    = (const float*)d_in[0];
    const int*   ei   = (const int*)  d_in[1];
    const float* lab  = (const float*)d_in[2];
    const float* lab2 = (const float*)d_in[3];
    const float* ew   = (const float*)d_in[4];
    const float* W0   = (const float*)d_in[5];
    const float* b0   = (const float*)d_in[6];
    const float* W1   = (const float*)d_in[7];
    const float* b1   = (const float*)d_in[8];
    const float* W2   = (const float*)d_in[9];
    const float* b2   = (const float*)d_in[10];
    const float* g0   = (const float*)d_in[11];
    const float* be0  = (const float*)d_in[12];
    const float* g1   = (const float*)d_in[13];
    const float* be1  = (const float*)d_in[14];
    float* out = (float*)d_out;

    const int* row = ei;
    const int* col = ei + EE;

    float *t1, *t2, *t3, *la, *lb;
    cudaGetSymbolAddress((void**)&t1, g_t1);
    cudaGetSymbolAddress((void**)&t2, g_t2);
    cudaGetSymbolAddress((void**)&t3, g_t3);
    cudaGetSymbolAddress((void**)&la, g_la);
    cudaGetSymbolAddress((void**)&lb, g_lb);
    // second LPA ping-pong pair carved from g_t1 (free during LPA stage)
    float* lc = t1;
    float* ld = t1 + (size_t)NN * OUTC;

    const int T = 256;

    // ---- CSR + normalization ----
    k_init_node<<<cdiv(NN, T), T>>>();
    k_deg_cnt<<<cdiv(EE, T), T>>>(row, ew);
    k_dinv<<<cdiv(NN, T), T>>>();
    k_scan<<<1, 1024>>>();
    k_scatter<<<cdiv(EE, T), T>>>(row, col, ew);

    dim3 gemm_grid_hid(cdiv(HIDC, 128), cdiv(NN, 128));
    dim3 gemm_grid_out(cdiv(OUTC, 128), cdiv(NN, 128));
    int elem256_grid = cdiv(NN * HIDC, T);
    int prop40_grid = cdiv(NN, 8);

    // ---- layer 0: x@W0 -> propagate(+b0) -> BN -> ReLU ----
    k_sgemm<<<gemm_grid_hid, T>>>(NN, HIDC, INC, x, W0, t1);
    k_prop256<<<NN, 256>>>(t1, t2, b0);
    k_zero_sums<<<1, HIDC>>>();
    k_bn_reduce<<<256, HIDC>>>(t2);
    k_bn_finalize<<<1, HIDC>>>(g0, be0);
    k_bn_apply_relu<<<elem256_grid, T>>>(t2, t1);

    // ---- layer 1: h@W1 -> propagate(+b1) -> BN -> ReLU ----
    k_sgemm<<<gemm_grid_hid, T>>>(NN, HIDC, HIDC, t1, W1, t2);
    k_prop256<<<NN, 256>>>(t2, t1, b1);
    k_zero_sums<<<1, HIDC>>>();
    k_bn_reduce<<<256, HIDC>>>(t1);
    k_bn_finalize<<<1, HIDC>>>(g1, be1);
    k_bn_apply_relu<<<elem256_grid, T>>>(t1, t2);

    // ---- output conv: h@W2 -> propagate(+b2) -> d_out[0 : NN*40] ----
    k_sgemm<<<gemm_grid_out, T>>>(NN, OUTC, HIDC, t2, W2, t3);
    k_prop40<false><<<prop40_grid, 256>>>(t3, nullptr, out, nullptr, b2);

    // ---- LPA: 3 fused dual propagates ----
    float* yh1 = out + (size_t)NN * OUTC;
    float* yh2 = out + (size_t)2 * NN * OUTC;

    k_prop40<true><<<prop40_grid, 256>>>(lab, lab2, la, lb, nullptr);
    k_prop40<true><<<prop40_grid, 256>>>(la, lb, lc, ld, nullptr);
    k_prop40<true><<<prop40_grid, 256>>>(lc, ld, yh1, yh2, nullptr);
}

// round 3
// speedup vs baseline: 2.2084x; 1.2954x over previous
#include <cuda_runtime.h>
#include <cstddef>

#define NN   50000
#define EE   800000
#define INC  512
#define HIDC 256
#define OUTC 40
#define BN_EPS 1e-5f
#define NP   196        // ceil(NN/256) scan partials

// ---------------- scratch (device globals; no allocation allowed) ----------------
__device__ float g_deg[NN];
__device__ float g_dinv[NN];
__device__ int   g_cnt[NN];
__device__ int   g_rowstart[NN + 1];
__device__ int   g_cursor[NN];
__device__ int   g_part[NP];
__device__ int   g_partscan[NP];
__device__ int   g_ecol[EE];
__device__ float g_ew2[EE];          // w * dinv[col]  (sorted by row)
__device__ float g_t1[NN * HIDC];
__device__ float g_t2[NN * HIDC];
__device__ float g_t3[NN * OUTC];
__device__ float g_la[NN * OUTC];
__device__ float g_lb[NN * OUTC];
__device__ float g_sum[HIDC];
__device__ float g_sumsq[HIDC];
__device__ float g_scale[HIDC];
__device__ float g_shift[HIDC];

// ---------------- CSR construction ----------------
__global__ void k_init_node() {
    int i = blockIdx.x * blockDim.x + threadIdx.x;
    if (i < NN) { g_deg[i] = 1.0f; g_cnt[i] = 0; }   // self-loop weight
}

__global__ void k_deg_cnt(const int* __restrict__ row, const float* __restrict__ w) {
    int e = blockIdx.x * blockDim.x + threadIdx.x;
    if (e < EE) {
        int r = row[e];
        atomicAdd(&g_deg[r], w[e]);
        atomicAdd(&g_cnt[r], 1);
    }
}

__global__ void k_dinv() {
    int i = blockIdx.x * blockDim.x + threadIdx.x;
    if (i < NN) {
        float d = g_deg[i];
        g_dinv[i] = d > 0.f ? rsqrtf(fmaxf(d, 1e-12f)) : 0.f;
    }
}

// -------- 3-phase parallel scan --------
__device__ __forceinline__ int block_incl_scan(int val, int* warp_sums) {
    int lane = threadIdx.x & 31, wid = threadIdx.x >> 5;
    int v = val;
#pragma unroll
    for (int o = 1; o < 32; o <<= 1) {
        int n = __shfl_up_sync(0xffffffffu, v, o);
        if (lane >= o) v += n;
    }
    if (lane == 31) warp_sums[wid] = v;
    __syncthreads();
    if (wid == 0) {
        int w = (lane < 8) ? warp_sums[lane] : 0;
#pragma unroll
        for (int o = 1; o < 8; o <<= 1) {
            int n = __shfl_up_sync(0xffffffffu, w, o);
            if (lane >= o) w += n;
        }
        if (lane < 8) warp_sums[lane] = w;
    }
    __syncthreads();
    return v + (wid > 0 ? warp_sums[wid - 1] : 0);
}

__global__ void k_scan1() {
    __shared__ int ws[8];
    int i = blockIdx.x * 256 + threadIdx.x;
    int val = (i < NN) ? g_cnt[i] : 0;
    int incl = block_incl_scan(val, ws);
    if (threadIdx.x == 255) g_part[blockIdx.x] = incl;
}

__global__ void k_scan2() {
    __shared__ int ws[8];
    int t = threadIdx.x;
    int val = (t < NP) ? g_part[t] : 0;
    int incl = block_incl_scan(val, ws);
    if (t < NP) g_partscan[t] = incl - val;   // exclusive
}

__global__ void k_scan3() {
    __shared__ int ws[8];
    int i = blockIdx.x * 256 + threadIdx.x;
    int val = (i < NN) ? g_cnt[i] : 0;
    int incl = block_incl_scan(val, ws);
    int excl = incl - val + g_partscan[blockIdx.x];
    if (i < NN) { g_rowstart[i] = excl; g_cursor[i] = excl; }
    if (i == 0) g_rowstart[NN] = EE;
}

__global__ void k_scatter(const int* __restrict__ row, const int* __restrict__ col,
                          const float* __restrict__ w) {
    int e = blockIdx.x * blockDim.x + threadIdx.x;
    if (e < EE) {
        int r = row[e];
        int c = col[e];
        int pos = atomicAdd(&g_cursor[r], 1);
        g_ecol[pos] = c;
        g_ew2[pos] = w[e] * g_dinv[c];
    }
}

// ---------------- propagate C=256: block per node, thread per channel ----------------
__global__ void __launch_bounds__(256) k_prop256(const float* __restrict__ h,
                                                 float* __restrict__ out,
                                                 const float* __restrict__ bias) {
    int i = blockIdx.x;
    int c = threadIdx.x;
    __shared__ int scol[256];
    __shared__ float sw[256];

    int s = g_rowstart[i], e = g_rowstart[i + 1];
    float hc = h[((size_t)i << 8) + c];
    float acc0 = 0.f, acc1 = 0.f, acc2 = 0.f, acc3 = 0.f;

    for (int base = s; base < e; base += 256) {
        int n = e - base; if (n > 256) n = 256;
        if (c < n) { scol[c] = g_ecol[base + c]; sw[c] = g_ew2[base + c]; }
        __syncthreads();
        int j = 0;
        for (; j + 3 < n; j += 4) {
            acc0 += sw[j + 0] * h[((size_t)scol[j + 0] << 8) + c];
            acc1 += sw[j + 1] * h[((size_t)scol[j + 1] << 8) + c];
            acc2 += sw[j + 2] * h[((size_t)scol[j + 2] << 8) + c];
            acc3 += sw[j + 3] * h[((size_t)scol[j + 3] << 8) + c];
        }
        for (; j < n; j++)
            acc0 += sw[j] * h[((size_t)scol[j] << 8) + c];
        __syncthreads();
    }
    float di = g_dinv[i];
    float acc = (acc0 + acc1) + (acc2 + acc3);
    float b = bias ? bias[c] : 0.f;
    out[((size_t)i << 8) + c] = di * di * hc + di * acc + b;
}

// ---------------- propagate C=40: warp per node; optional second matrix ----------------
template <bool DUAL>
__global__ void __launch_bounds__(256) k_prop40(const float* __restrict__ ha,
                                                const float* __restrict__ hb,
                                                float* __restrict__ oa,
                                                float* __restrict__ ob,
                                                const float* __restrict__ bias) {
    int warp = threadIdx.x >> 5;
    int lane = threadIdx.x & 31;
    int i = blockIdx.x * 8 + warp;
    if (i >= NN) return;

    int s = g_rowstart[i], e = g_rowstart[i + 1];
    float a0 = 0.f, a1 = 0.f, b0 = 0.f, b1 = 0.f;

    for (int p = s; p < e; p++) {
        int c = g_ecol[p];
        float w = g_ew2[p];
        const float* ra = ha + (size_t)c * OUTC;
        a0 += w * ra[lane];
        if (lane < 8) a1 += w * ra[lane + 32];
        if (DUAL) {
            const float* rb = hb + (size_t)c * OUTC;
            b0 += w * rb[lane];
            if (lane < 8) b1 += w * rb[lane + 32];
        }
    }
    float di = g_dinv[i];
    size_t off = (size_t)i * OUTC;
    float bs0 = bias ? bias[lane] : 0.f;
    float bs1 = (bias && lane < 8) ? bias[lane + 32] : 0.f;

    oa[off + lane] = di * di * ha[off + lane] + di * a0 + bs0;
    if (lane < 8)
        oa[off + lane + 32] = di * di * ha[off + lane + 32] + di * a1 + bs1;
    if (DUAL) {
        ob[off + lane] = di * di * hb[off + lane] + di * b0;
        if (lane < 8)
            ob[off + lane + 32] = di * di * hb[off + lane + 32] + di * b1;
    }
}

// ---------------- batchnorm (C = 256) ----------------
__global__ void k_zero_sums() {
    int c = threadIdx.x;
    g_sum[c] = 0.f;
    g_sumsq[c] = 0.f;
}

__global__ void k_bn_reduce(const float* __restrict__ h) {
    int c = threadIdx.x;
    float s = 0.f, sq = 0.f;
    for (int i = blockIdx.x; i < NN; i += gridDim.x) {
        float v = h[((size_t)i << 8) + c];
        s += v;
        sq += v * v;
    }
    atomicAdd(&g_sum[c], s);
    atomicAdd(&g_sumsq[c], sq);
}

__global__ void k_bn_finalize(const float* __restrict__ gamma, const float* __restrict__ beta) {
    int c = threadIdx.x;
    float mean = g_sum[c] * (1.0f / NN);
    float var = g_sumsq[c] * (1.0f / NN) - mean * mean;
    var = fmaxf(var, 0.f);
    float inv = rsqrtf(var + BN_EPS);
    float sc = gamma[c] * inv;
    g_scale[c] = sc;
    g_shift[c] = beta[c] - mean * sc;
}

// ---------------- tf32x3 tensor-core GEMM ----------------
// C[M,N] = op(A)[M,K] @ B[K,N]; op = identity or fused BN(scale,shift)+ReLU per K-channel.
// Block 128x128x16, 8 warps, warp tile 32x64, mma.m16n8k8 tf32, hi/lo split (3 passes).

__device__ __forceinline__ void split_tf32(float x, unsigned& hi, unsigned& lo) {
    unsigned h;
    asm("cvt.rna.tf32.f32 %0, %1;" : "=r"(h) : "f"(x));
    float r = x - __uint_as_float(h);
    unsigned l;
    asm("cvt.rna.tf32.f32 %0, %1;" : "=r"(l) : "f"(r));
    hi = h; lo = l;
}

__device__ __forceinline__ void mma_tf32(float* c, const unsigned* a, const unsigned* b) {
    asm volatile(
        "mma.sync.aligned.m16n8k8.row.col.f32.tf32.tf32.f32 "
        "{%0,%1,%2,%3}, {%4,%5,%6,%7}, {%8,%9}, {%0,%1,%2,%3};"
        : "+f"(c[0]), "+f"(c[1]), "+f"(c[2]), "+f"(c[3])
        : "r"(a[0]), "r"(a[1]), "r"(a[2]), "r"(a[3]), "r"(b[0]), "r"(b[1]));
}

#define AS_STRIDE 36   // conflict-free fragment loads: bank = g*4+tig (bijective)
#define BS_STRIDE 132

template <bool FUSE_BN>
__global__ void __launch_bounds__(256) k_mma_gemm(int M, int N, int K,
                                                  const float* __restrict__ A,
                                                  const float* __restrict__ B,
                                                  float* __restrict__ C) {
    __shared__ float As[128 * AS_STRIDE];
    __shared__ float Bs[16 * BS_STRIDE];

    int tid = threadIdx.x;
    int bm = blockIdx.y * 128, bn = blockIdx.x * 128;

    int aRow = tid >> 2;            // 0..63  (4 threads per row, 16 K each)
    int aK   = (tid & 3) * 4;
    int bRow = tid >> 5;            // 0..7
    int bCol = (tid & 31) * 4;

    int warp = tid >> 5, lane = tid & 31;
    int wm = (warp >> 1) * 32;      // warp m offset within block (0,32,64,96)
    int wn = (warp & 1) * 64;       // warp n offset (0,64)
    int groupID = lane >> 2, tig = lane & 3;

    float acc[2][8][4];
#pragma unroll
    for (int mi = 0; mi < 2; mi++)
#pragma unroll
        for (int ni = 0; ni < 8; ni++)
#pragma unroll
            for (int q = 0; q < 4; q++) acc[mi][ni][q] = 0.f;

    for (int k0 = 0; k0 < K; k0 += 16) {
        // ---- load A tile (rows bm..bm+127, K cols k0..k0+15) ----
#pragma unroll
        for (int r = 0; r < 2; r++) {
            int row = aRow + r * 64;
            int grow = bm + row;
            float4 v = make_float4(0.f, 0.f, 0.f, 0.f);
            if (grow < M) v = *(const float4*)(A + (size_t)grow * K + k0 + aK);
            if (FUSE_BN) {
                int k = k0 + aK;
                v.x = fmaxf(v.x * g_scale[k + 0] + g_shift[k + 0], 0.f);
                v.y = fmaxf(v.y * g_scale[k + 1] + g_shift[k + 1], 0.f);
                v.z = fmaxf(v.z * g_scale[k + 2] + g_shift[k + 2], 0.f);
                v.w = fmaxf(v.w * g_scale[k + 3] + g_shift[k + 3], 0.f);
            }
            *(float4*)(As + row * AS_STRIDE + aK) = v;
        }
        // ---- load B tile (K rows k0..k0+15, cols bn..bn+127) ----
#pragma unroll
        for (int r = 0; r < 2; r++) {
            int krow = bRow + r * 8;
            int gn = bn + bCol;
            const float* Bp = B + (size_t)(k0 + krow) * N + gn;
            float4 v = make_float4(0.f, 0.f, 0.f, 0.f);
            if (gn + 3 < N) {
                v = *(const float4*)Bp;
            } else {
                if (gn + 0 < N) v.x = Bp[0];
                if (gn + 1 < N) v.y = Bp[1];
                if (gn + 2 < N) v.z = Bp[2];
                if (gn + 3 < N) v.w = Bp[3];
            }
            *(float4*)(Bs + krow * BS_STRIDE + bCol) = v;
        }
        __syncthreads();

#pragma unroll
        for (int ks = 0; ks < 16; ks += 8) {
            // A fragments (2 m-tiles), hi/lo split
            unsigned ah[2][4], al[2][4];
#pragma unroll
            for (int mi = 0; mi < 2; mi++) {
                int r0 = wm + mi * 16 + groupID;
                float x0 = As[r0 * AS_STRIDE + ks + tig];
                float x1 = As[(r0 + 8) * AS_STRIDE + ks + tig];
                float x2 = As[r0 * AS_STRIDE + ks + tig + 4];
                float x3 = As[(r0 + 8) * AS_STRIDE + ks + tig + 4];
                split_tf32(x0, ah[mi][0], al[mi][0]);
                split_tf32(x1, ah[mi][1], al[mi][1]);
                split_tf32(x2, ah[mi][2], al[mi][2]);
                split_tf32(x3, ah[mi][3], al[mi][3]);
            }
#pragma unroll
            for (int ni = 0; ni < 8; ni++) {
                int c = wn + ni * 8 + groupID;
                float y0 = Bs[(ks + tig) * BS_STRIDE + c];
                float y1 = Bs[(ks + tig + 4) * BS_STRIDE + c];
                unsigned bh[2], bl[2];
                split_tf32(y0, bh[0], bl[0]);
                split_tf32(y1, bh[1], bl[1]);
#pragma unroll
                for (int mi = 0; mi < 2; mi++) {
                    mma_tf32(acc[mi][ni], ah[mi], bh);
                    mma_tf32(acc[mi][ni], ah[mi], bl);
                    mma_tf32(acc[mi][ni], al[mi], bh);
                }
            }
        }
        __syncthreads();
    }

    // ---- store C ----
#pragma unroll
    for (int mi = 0; mi < 2; mi++) {
        int r0 = bm + wm + mi * 16 + groupID;
        int r1 = r0 + 8;
#pragma unroll
        for (int ni = 0; ni < 8; ni++) {
            int c0 = bn + wn + ni * 8 + 2 * tig;
            if (r0 < M) {
                if (c0 < N)     C[(size_t)r0 * N + c0]     = acc[mi][ni][0];
                if (c0 + 1 < N) C[(size_t)r0 * N + c0 + 1] = acc[mi][ni][1];
            }
            if (r1 < M) {
                if (c0 < N)     C[(size_t)r1 * N + c0]     = acc[mi][ni][2];
                if (c0 + 1 < N) C[(size_t)r1 * N + c0 + 1] = acc[mi][ni][3];
            }
        }
    }
}

// ---------------- host orchestration ----------------
static inline int cdiv(int a, int b) { return (a + b - 1) / b; }

extern "C" void kernel_launch(void* const* d_in, const int* in_sizes, int n_in,
                              void* d_out, int out_size) {
    const float* x    = (const float*)d_in[0];
    const int*   ei   = (const int*)  d_in[1];
    const float* lab  = (const float*)d_in[2];
    const float* lab2 = (const float*)d_in[3];
    const float* ew   = (const float*)d_in[4];
    const float* W0   = (const float*)d_in[5];
    const float* b0   = (const float*)d_in[6];
    const float* W1   = (const float*)d_in[7];
    const float* b1   = (const float*)d_in[8];
    const float* W2   = (const float*)d_in[9];
    const float* b2   = (const float*)d_in[10];
    const float* g0   = (const float*)d_in[11];
    const float* be0  = (const float*)d_in[12];
    const float* g1   = (const float*)d_in[13];
    const float* be1  = (const float*)d_in[14];
    float* out = (float*)d_out;

    const int* row = ei;
    const int* col = ei + EE;

    float *t1, *t2, *t3, *la, *lb;
    cudaGetSymbolAddress((void**)&t1, g_t1);
    cudaGetSymbolAddress((void**)&t2, g_t2);
    cudaGetSymbolAddress((void**)&t3, g_t3);
    cudaGetSymbolAddress((void**)&la, g_la);
    cudaGetSymbolAddress((void**)&lb, g_lb);
    float* lc = t1;                              // free during LPA stage
    float* ld = t1 + (size_t)NN * OUTC;

    const int T = 256;

    // ---- CSR + normalization ----
    k_init_node<<<cdiv(NN, T), T>>>();
    k_deg_cnt<<<cdiv(EE, T), T>>>(row, ew);
    k_dinv<<<cdiv(NN, T), T>>>();
    k_scan1<<<NP, 256>>>();
    k_scan2<<<1, 256>>>();
    k_scan3<<<NP, 256>>>();
    k_scatter<<<cdiv(EE, T), T>>>(row, col, ew);

    dim3 gemm_grid_hid(2, cdiv(NN, 128));   // N=256
    dim3 gemm_grid_out(1, cdiv(NN, 128));   // N=40
    int prop40_grid = cdiv(NN, 8);

    // ---- layer 0: x@W0 -> propagate(+b0) -> BN stats ----
    k_mma_gemm<false><<<gemm_grid_hid, T>>>(NN, HIDC, INC, x, W0, t1);
    k_prop256<<<NN, 256>>>(t1, t2, b0);
    k_zero_sums<<<1, HIDC>>>();
    k_bn_reduce<<<256, HIDC>>>(t2);
    k_bn_finalize<<<1, HIDC>>>(g0, be0);

    // ---- layer 1: relu(bn(t2))@W1 (fused in A load) -> propagate(+b1) -> BN stats ----
    k_mma_gemm<true><<<gemm_grid_hid, T>>>(NN, HIDC, HIDC, t2, W1, t1);
    k_prop256<<<NN, 256>>>(t1, t2, b1);
    k_zero_sums<<<1, HIDC>>>();
    k_bn_reduce<<<256, HIDC>>>(t2);
    k_bn_finalize<<<1, HIDC>>>(g1, be1);

    // ---- output conv: relu(bn(t2))@W2 (fused) -> propagate(+b2) -> d_out ----
    k_mma_gemm<true><<<gemm_grid_out, T>>>(NN, OUTC, HIDC, t2, W2, t3);
    k_prop40<false><<<prop40_grid, 256>>>(t3, nullptr, out, nullptr, b2);

    // ---- LPA: 3 fused dual propagates ----
    float* yh1 = out + (size_t)NN * OUTC;
    float* yh2 = out + (size_t)2 * NN * OUTC;

    k_prop40<true><<<prop40_grid, 256>>>(lab, lab2, la, lb, nullptr);
    k_prop40<true><<<prop40_grid, 256>>>(la, lb, lc, ld, nullptr);
    k_prop40<true><<<prop40_grid, 256>>>(lc, ld, yh1, yh2, nullptr);
}

// round 4
// speedup vs baseline: 2.7369x; 1.2393x over previous
#include <cuda_runtime.h>
#include <cuda_bf16.h>
#include <cstdint>
#include <cstddef>

#define NN   50000
#define EE   800000
#define INC  512
#define HIDC 256
#define OUTC 40
#define BN_EPS 1e-5f
#define NP   196        // ceil(NN/256) scan partials

// ---------------- scratch (device globals; no allocation allowed) ----------------
__device__ float g_deg[NN];
__device__ float g_dinv[NN];
__device__ int   g_cnt[NN];
__device__ int   g_rowstart[NN + 1];
__device__ int   g_cursor[NN];
__device__ int   g_part[NP];
__device__ int   g_partscan[NP];
__device__ int   g_ecol[EE];
__device__ float g_ew2[EE];          // w * dinv[col]  (sorted by row)
__device__ float g_t1[NN * HIDC];
__device__ float g_t2[NN * HIDC];
__device__ float g_t3[NN * OUTC];
__device__ float g_la[NN * OUTC];
__device__ float g_lb[NN * OUTC];
__device__ float g_sum[HIDC];
__device__ float g_sumsq[HIDC];
__device__ float g_scale[HIDC];
__device__ float g_shift[HIDC];

// ---------------- CSR construction ----------------
__global__ void k_init_node() {
    int i = blockIdx.x * blockDim.x + threadIdx.x;
    if (i < NN) { g_deg[i] = 1.0f; g_cnt[i] = 0; }   // self-loop weight
}

__global__ void k_deg_cnt(const int* __restrict__ row, const float* __restrict__ w) {
    int e = blockIdx.x * blockDim.x + threadIdx.x;
    if (e < EE) {
        int r = row[e];
        atomicAdd(&g_deg[r], w[e]);
        atomicAdd(&g_cnt[r], 1);
    }
}

__global__ void k_dinv() {
    int i = blockIdx.x * blockDim.x + threadIdx.x;
    if (i < NN) {
        float d = g_deg[i];
        g_dinv[i] = d > 0.f ? rsqrtf(fmaxf(d, 1e-12f)) : 0.f;
    }
}

// -------- 3-phase parallel scan --------
__device__ __forceinline__ int block_incl_scan(int val, int* warp_sums) {
    int lane = threadIdx.x & 31, wid = threadIdx.x >> 5;
    int v = val;
#pragma unroll
    for (int o = 1; o < 32; o <<= 1) {
        int n = __shfl_up_sync(0xffffffffu, v, o);
        if (lane >= o) v += n;
    }
    if (lane == 31) warp_sums[wid] = v;
    __syncthreads();
    if (wid == 0) {
        int w = (lane < 8) ? warp_sums[lane] : 0;
#pragma unroll
        for (int o = 1; o < 8; o <<= 1) {
            int n = __shfl_up_sync(0xffffffffu, w, o);
            if (lane >= o) w += n;
        }
        if (lane < 8) warp_sums[lane] = w;
    }
    __syncthreads();
    return v + (wid > 0 ? warp_sums[wid - 1] : 0);
}

__global__ void k_scan1() {
    __shared__ int ws[8];
    int i = blockIdx.x * 256 + threadIdx.x;
    int val = (i < NN) ? g_cnt[i] : 0;
    int incl = block_incl_scan(val, ws);
    if (threadIdx.x == 255) g_part[blockIdx.x] = incl;
}

__global__ void k_scan2() {
    __shared__ int ws[8];
    int t = threadIdx.x;
    int val = (t < NP) ? g_part[t] : 0;
    int incl = block_incl_scan(val, ws);
    if (t < NP) g_partscan[t] = incl - val;   // exclusive
}

__global__ void k_scan3() {
    __shared__ int ws[8];
    int i = blockIdx.x * 256 + threadIdx.x;
    int val = (i < NN) ? g_cnt[i] : 0;
    int incl = block_incl_scan(val, ws);
    int excl = incl - val + g_partscan[blockIdx.x];
    if (i < NN) { g_rowstart[i] = excl; g_cursor[i] = excl; }
    if (i == 0) g_rowstart[NN] = EE;
}

__global__ void k_scatter(const int* __restrict__ row, const int* __restrict__ col,
                          const float* __restrict__ w) {
    int e = blockIdx.x * blockDim.x + threadIdx.x;
    if (e < EE) {
        int r = row[e];
        int c = col[e];
        int pos = atomicAdd(&g_cursor[r], 1);
        g_ecol[pos] = c;
        g_ew2[pos] = w[e] * g_dinv[c];
    }
}

// ---------------- propagate C=256: block per node, thread per channel ----------------
__global__ void __launch_bounds__(256) k_prop256(const float* __restrict__ h,
                                                 float* __restrict__ out,
                                                 const float* __restrict__ bias) {
    int i = blockIdx.x;
    int c = threadIdx.x;
    __shared__ int scol[256];
    __shared__ float sw[256];

    int s = g_rowstart[i], e = g_rowstart[i + 1];
    float hc = h[((size_t)i << 8) + c];
    float acc0 = 0.f, acc1 = 0.f, acc2 = 0.f, acc3 = 0.f;

    for (int base = s; base < e; base += 256) {
        int n = e - base; if (n > 256) n = 256;
        if (c < n) { scol[c] = g_ecol[base + c]; sw[c] = g_ew2[base + c]; }
        __syncthreads();
        int j = 0;
        for (; j + 3 < n; j += 4) {
            acc0 += sw[j + 0] * h[((size_t)scol[j + 0] << 8) + c];
            acc1 += sw[j + 1] * h[((size_t)scol[j + 1] << 8) + c];
            acc2 += sw[j + 2] * h[((size_t)scol[j + 2] << 8) + c];
            acc3 += sw[j + 3] * h[((size_t)scol[j + 3] << 8) + c];
        }
        for (; j < n; j++)
            acc0 += sw[j] * h[((size_t)scol[j] << 8) + c];
        __syncthreads();
    }
    float di = g_dinv[i];
    float acc = (acc0 + acc1) + (acc2 + acc3);
    float b = bias ? bias[c] : 0.f;
    out[((size_t)i << 8) + c] = di * di * hc + di * acc + b;
}

// ---------------- propagate C=40: warp per node; optional second matrix ----------------
template <bool DUAL>
__global__ void __launch_bounds__(256) k_prop40(const float* __restrict__ ha,
                                                const float* __restrict__ hb,
                                                float* __restrict__ oa,
                                                float* __restrict__ ob,
                                                const float* __restrict__ bias) {
    int warp = threadIdx.x >> 5;
    int lane = threadIdx.x & 31;
    int i = blockIdx.x * 8 + warp;
    if (i >= NN) return;

    int s = g_rowstart[i], e = g_rowstart[i + 1];
    float a0 = 0.f, a1 = 0.f, b0 = 0.f, b1 = 0.f;

    for (int p = s; p < e; p++) {
        int c = g_ecol[p];
        float w = g_ew2[p];
        const float* ra = ha + (size_t)c * OUTC;
        a0 += w * ra[lane];
        if (lane < 8) a1 += w * ra[lane + 32];
        if (DUAL) {
            const float* rb = hb + (size_t)c * OUTC;
            b0 += w * rb[lane];
            if (lane < 8) b1 += w * rb[lane + 32];
        }
    }
    float di = g_dinv[i];
    size_t off = (size_t)i * OUTC;
    float bs0 = bias ? bias[lane] : 0.f;
    float bs1 = (bias && lane < 8) ? bias[lane + 32] : 0.f;

    oa[off + lane] = di * di * ha[off + lane] + di * a0 + bs0;
    if (lane < 8)
        oa[off + lane + 32] = di * di * ha[off + lane + 32] + di * a1 + bs1;
    if (DUAL) {
        ob[off + lane] = di * di * hb[off + lane] + di * b0;
        if (lane < 8)
            ob[off + lane + 32] = di * di * hb[off + lane + 32] + di * b1;
    }
}

// ---------------- batchnorm (C = 256) ----------------
__global__ void k_zero_sums() {
    int c = threadIdx.x;
    g_sum[c] = 0.f;
    g_sumsq[c] = 0.f;
}

__global__ void k_bn_reduce(const float* __restrict__ h) {
    int c = threadIdx.x;
    float s = 0.f, sq = 0.f;
    for (int i = blockIdx.x; i < NN; i += gridDim.x) {
        float v = h[((size_t)i << 8) + c];
        s += v;
        sq += v * v;
    }
    atomicAdd(&g_sum[c], s);
    atomicAdd(&g_sumsq[c], sq);
}

__global__ void k_bn_finalize(const float* __restrict__ gamma, const float* __restrict__ beta) {
    int c = threadIdx.x;
    float mean = g_sum[c] * (1.0f / NN);
    float var = g_sumsq[c] * (1.0f / NN) - mean * mean;
    var = fmaxf(var, 0.f);
    float inv = rsqrtf(var + BN_EPS);
    float sc = gamma[c] * inv;
    g_scale[c] = sc;
    g_shift[c] = beta[c] - mean * sc;
}

// ---------------- bf16x3 split tensor-core GEMM ----------------
// C[M,N] = op(A)[M,K] @ B[K,N]; op = identity or fused BN(scale,shift)+ReLU on K channels.
// Block 128x128x16, 8 warps, warp tile 32x64, mma.m16n8k16 bf16, hi/lo split:
// A*B ~= Ah*Bh + Al*Bh + Ah*Bl  (AlBl ~ 2^-18 relative, dropped)

#define AS_ST 24    // bf16 units per A row (16 data + 8 pad): conflict-free ldmatrix
#define BS_ST 136   // bf16 units per B k-row (128 data + 8 pad)

__device__ __forceinline__ void ldsm_x4(uint32_t* r, uint32_t addr) {
    asm volatile("ldmatrix.sync.aligned.m8n8.x4.shared.b16 {%0,%1,%2,%3}, [%4];"
                 : "=r"(r[0]), "=r"(r[1]), "=r"(r[2]), "=r"(r[3]) : "r"(addr));
}
__device__ __forceinline__ void ldsm_x2_t(uint32_t* r, uint32_t addr) {
    asm volatile("ldmatrix.sync.aligned.m8n8.x2.trans.shared.b16 {%0,%1}, [%2];"
                 : "=r"(r[0]), "=r"(r[1]) : "r"(addr));
}
__device__ __forceinline__ void mma_bf16(float* c, const uint32_t* a, const uint32_t* b) {
    asm volatile(
        "mma.sync.aligned.m16n8k16.row.col.f32.bf16.bf16.f32 "
        "{%0,%1,%2,%3}, {%4,%5,%6,%7}, {%8,%9}, {%0,%1,%2,%3};"
        : "+f"(c[0]), "+f"(c[1]), "+f"(c[2]), "+f"(c[3])
        : "r"(a[0]), "r"(a[1]), "r"(a[2]), "r"(a[3]), "r"(b[0]), "r"(b[1]));
}

// split one float into hi/lo bf16
__device__ __forceinline__ void split_bf16(float x, __nv_bfloat16& h, __nv_bfloat16& l) {
    h = __float2bfloat16_rn(x);
    l = __float2bfloat16_rn(x - __bfloat162float(h));
}

template <bool FUSE_BN>
__global__ void __launch_bounds__(256) k_mma_bf16(int M, int N, int K,
                                                  const float* __restrict__ A,
                                                  const float* __restrict__ B,
                                                  float* __restrict__ C) {
    __shared__ __nv_bfloat16 Ah[128 * AS_ST];
    __shared__ __nv_bfloat16 Al[128 * AS_ST];
    __shared__ __nv_bfloat16 Bh[16 * BS_ST];
    __shared__ __nv_bfloat16 Bl[16 * BS_ST];

    int tid = threadIdx.x;
    int bm = blockIdx.y * 128, bn = blockIdx.x * 128;

    // loaders: A thread -> row aRow, cols aK..aK+7 (2 float4); B thread -> k bK, cols bN..bN+7
    int aRow = tid >> 1;
    int aK   = (tid & 1) * 8;
    int bK   = tid >> 4;
    int bN   = (tid & 15) * 8;

    int warp = tid >> 5, lane = tid & 31;
    int wm = (warp >> 1) * 32;
    int wn = (warp & 1) * 64;
    int groupID = lane >> 2, tig = lane & 3;

    uint32_t sAh = (uint32_t)__cvta_generic_to_shared(Ah);
    uint32_t sAl = (uint32_t)__cvta_generic_to_shared(Al);
    uint32_t sBh = (uint32_t)__cvta_generic_to_shared(Bh);
    uint32_t sBl = (uint32_t)__cvta_generic_to_shared(Bl);

    // ldmatrix addresses
    uint32_t aAddrH[2], aAddrL[2];
#pragma unroll
    for (int mi = 0; mi < 2; mi++) {
        int ar = wm + mi * 16 + (lane & 7) + ((lane >> 3) & 1) * 8;
        int ako = (lane & 16) ? 8 : 0;
        uint32_t off = (uint32_t)(ar * AS_ST + ako) * 2;
        aAddrH[mi] = sAh + off;
        aAddrL[mi] = sAl + off;
    }
    int bk = ((lane & 15) >> 3) * 8 + (lane & 7);   // lanes 16-31 mirror 0-15 (unused by x2)
    uint32_t bRowOffH = sBh + (uint32_t)(bk * BS_ST) * 2;
    uint32_t bRowOffL = sBl + (uint32_t)(bk * BS_ST) * 2;

    float acc[2][8][4];
#pragma unroll
    for (int mi = 0; mi < 2; mi++)
#pragma unroll
        for (int ni = 0; ni < 8; ni++)
#pragma unroll
            for (int q = 0; q < 4; q++) acc[mi][ni][q] = 0.f;

    float4 aPf[2], bPf[2];

    // ---- prefetch tile 0 ----
    {
        int grow = bm + aRow;
#pragma unroll
        for (int q = 0; q < 2; q++) {
            aPf[q] = make_float4(0.f, 0.f, 0.f, 0.f);
            if (grow < M) aPf[q] = *(const float4*)(A + (size_t)grow * K + aK + q * 4);
        }
#pragma unroll
        for (int q = 0; q < 2; q++) {
            int gn = bn + bN + q * 4;
            float4 v = make_float4(0.f, 0.f, 0.f, 0.f);
            if (gn + 3 < N) v = *(const float4*)(B + (size_t)bK * N + gn);
            else {
                const float* Bp = B + (size_t)bK * N + gn;
                if (gn + 0 < N) v.x = Bp[0];
                if (gn + 1 < N) v.y = Bp[1];
                if (gn + 2 < N) v.z = Bp[2];
            }
            bPf[q] = v;
        }
    }

    for (int k0 = 0; k0 < K; k0 += 16) {
        // ---- convert + store current tile to smem ----
#pragma unroll
        for (int q = 0; q < 2; q++) {
            float4 v = aPf[q];
            if (FUSE_BN) {
                int k = k0 + aK + q * 4;
                v.x = fmaxf(v.x * g_scale[k + 0] + g_shift[k + 0], 0.f);
                v.y = fmaxf(v.y * g_scale[k + 1] + g_shift[k + 1], 0.f);
                v.z = fmaxf(v.z * g_scale[k + 2] + g_shift[k + 2], 0.f);
                v.w = fmaxf(v.w * g_scale[k + 3] + g_shift[k + 3], 0.f);
            }
            __nv_bfloat16 h0, l0, h1, l1, h2, l2, h3, l3;
            split_bf16(v.x, h0, l0); split_bf16(v.y, h1, l1);
            split_bf16(v.z, h2, l2); split_bf16(v.w, h3, l3);
            int off = aRow * AS_ST + aK + q * 4;
            *(__nv_bfloat162*)(Ah + off)     = __nv_bfloat162(h0, h1);
            *(__nv_bfloat162*)(Ah + off + 2) = __nv_bfloat162(h2, h3);
            *(__nv_bfloat162*)(Al + off)     = __nv_bfloat162(l0, l1);
            *(__nv_bfloat162*)(Al + off + 2) = __nv_bfloat162(l2, l3);
        }
#pragma unroll
        for (int q = 0; q < 2; q++) {
            float4 v = bPf[q];
            __nv_bfloat16 h0, l0, h1, l1, h2, l2, h3, l3;
            split_bf16(v.x, h0, l0); split_bf16(v.y, h1, l1);
            split_bf16(v.z, h2, l2); split_bf16(v.w, h3, l3);
            int off = bK * BS_ST + bN + q * 4;
            *(__nv_bfloat162*)(Bh + off)     = __nv_bfloat162(h0, h1);
            *(__nv_bfloat162*)(Bh + off + 2) = __nv_bfloat162(h2, h3);
            *(__nv_bfloat162*)(Bl + off)     = __nv_bfloat162(l0, l1);
            *(__nv_bfloat162*)(Bl + off + 2) = __nv_bfloat162(l2, l3);
        }
        __syncthreads();

        // ---- prefetch next tile (LDG latency hidden behind mma below) ----
        if (k0 + 16 < K) {
            int grow = bm + aRow;
#pragma unroll
            for (int q = 0; q < 2; q++) {
                aPf[q] = make_float4(0.f, 0.f, 0.f, 0.f);
                if (grow < M) aPf[q] = *(const float4*)(A + (size_t)grow * K + k0 + 16 + aK + q * 4);
            }
#pragma unroll
            for (int q = 0; q < 2; q++) {
                int gn = bn + bN + q * 4;
                float4 v = make_float4(0.f, 0.f, 0.f, 0.f);
                if (gn + 3 < N) v = *(const float4*)(B + (size_t)(k0 + 16 + bK) * N + gn);
                else {
                    const float* Bp = B + (size_t)(k0 + 16 + bK) * N + gn;
                    if (gn + 0 < N) v.x = Bp[0];
                    if (gn + 1 < N) v.y = Bp[1];
                    if (gn + 2 < N) v.z = Bp[2];
                }
                bPf[q] = v;
            }
        }

        // ---- fragments + mma ----
        uint32_t ah[2][4], al[2][4];
#pragma unroll
        for (int mi = 0; mi < 2; mi++) {
            ldsm_x4(ah[mi], aAddrH[mi]);
            ldsm_x4(al[mi], aAddrL[mi]);
        }
#pragma unroll
        for (int ni = 0; ni < 8; ni++) {
            uint32_t coff = (uint32_t)(wn + ni * 8) * 2;
            uint32_t bh[2], bl[2];
            ldsm_x2_t(bh, bRowOffH + coff);
            ldsm_x2_t(bl, bRowOffL + coff);
#pragma unroll
            for (int mi = 0; mi < 2; mi++) {
                mma_bf16(acc[mi][ni], ah[mi], bh);
                mma_bf16(acc[mi][ni], al[mi], bh);
                mma_bf16(acc[mi][ni], ah[mi], bl);
            }
        }
        __syncthreads();
    }

    // ---- store C ----
#pragma unroll
    for (int mi = 0; mi < 2; mi++) {
        int r0 = bm + wm + mi * 16 + groupID;
        int r1 = r0 + 8;
#pragma unroll
        for (int ni = 0; ni < 8; ni++) {
            int c0 = bn + wn + ni * 8 + 2 * tig;
            if (r0 < M) {
                if (c0 < N)     C[(size_t)r0 * N + c0]     = acc[mi][ni][0];
                if (c0 + 1 < N) C[(size_t)r0 * N + c0 + 1] = acc[mi][ni][1];
            }
            if (r1 < M) {
                if (c0 < N)     C[(size_t)r1 * N + c0]     = acc[mi][ni][2];
                if (c0 + 1 < N) C[(size_t)r1 * N + c0 + 1] = acc[mi][ni][3];
            }
        }
    }
}

// ---------------- host orchestration ----------------
static inline int cdiv(int a, int b) { return (a + b - 1) / b; }

extern "C" void kernel_launch(void* const* d_in, const int* in_sizes, int n_in,
                              void* d_out, int out_size) {
    const float* x    = (const float*)d_in[0];
    const int*   ei   = (const int*)  d_in[1];
    const float* lab  = (const float*)d_in[2];
    const float* lab2 = (const float*)d_in[3];
    const float* ew   = (const float*)d_in[4];
    const float* W0   = (const float*)d_in[5];
    const float* b0   = (const float*)d_in[6];
    const float* W1   = (const float*)d_in[7];
    const float* b1   = (const float*)d_in[8];
    const float* W2   = (const float*)d_in[9];
    const float* b2   = (const float*)d_in[10];
    const float* g0   = (const float*)d_in[11];
    const float* be0  = (const float*)d_in[12];
    const float* g1   = (const float*)d_in[13];
    const float* be1  = (const float*)d_in[14];
    float* out = (float*)d_out;

    const int* row = ei;
    const int* col = ei + EE;

    float *t1, *t2, *t3, *la, *lb;
    cudaGetSymbolAddress((void**)&t1, g_t1);
    cudaGetSymbolAddress((void**)&t2, g_t2);
    cudaGetSymbolAddress((void**)&t3, g_t3);
    cudaGetSymbolAddress((void**)&la, g_la);
    cudaGetSymbolAddress((void**)&lb, g_lb);
    float* lc = t1;                              // free during LPA stage
    float* ld = t1 + (size_t)NN * OUTC;

    const int T = 256;

    // ---- CSR + normalization ----
    k_init_node<<<cdiv(NN, T), T>>>();
    k_deg_cnt<<<cdiv(EE, T), T>>>(row, ew);
    k_dinv<<<cdiv(NN, T), T>>>();
    k_scan1<<<NP, 256>>>();
    k_scan2<<<1, 256>>>();
    k_scan3<<<NP, 256>>>();
    k_scatter<<<cdiv(EE, T), T>>>(row, col, ew);

    dim3 gemm_grid_hid(2, cdiv(NN, 128));   // N=256
    dim3 gemm_grid_out(1, cdiv(NN, 128));   // N=40
    int prop40_grid = cdiv(NN, 8);

    // ---- layer 0: x@W0 -> propagate(+b0) -> BN stats ----
    k_mma_bf16<false><<<gemm_grid_hid, T>>>(NN, HIDC, INC, x, W0, t1);
    k_prop256<<<NN, 256>>>(t1, t2, b0);
    k_zero_sums<<<1, HIDC>>>();
    k_bn_reduce<<<256, HIDC>>>(t2);
    k_bn_finalize<<<1, HIDC>>>(g0, be0);

    // ---- layer 1: relu(bn(t2))@W1 (fused in A load) -> propagate(+b1) -> BN stats ----
    k_mma_bf16<true><<<gemm_grid_hid, T>>>(NN, HIDC, HIDC, t2, W1, t1);
    k_prop256<<<NN, 256>>>(t1, t2, b1);
    k_zero_sums<<<1, HIDC>>>();
    k_bn_reduce<<<256, HIDC>>>(t2);
    k_bn_finalize<<<1, HIDC>>>(g1, be1);

    // ---- output conv: relu(bn(t2))@W2 (fused) -> propagate(+b2) -> d_out ----
    k_mma_bf16<true><<<gemm_grid_out, T>>>(NN, OUTC, HIDC, t2, W2, t3);
    k_prop40<false><<<prop40_grid, 256>>>(t3, nullptr, out, nullptr, b2);

    // ---- LPA: 3 fused dual propagates ----
    float* yh1 = out + (size_t)NN * OUTC;
    float* yh2 = out + (size_t)2 * NN * OUTC;

    k_prop40<true><<<prop40_grid, 256>>>(lab, lab2, la, lb, nullptr);
    k_prop40<true><<<prop40_grid, 256>>>(la, lb, lc, ld, nullptr);
    k_prop40<true><<<prop40_grid, 256>>>(lc, ld, yh1, yh2, nullptr);
}